// round 1
// baseline (speedup 1.0000x reference)
#include <cuda_runtime.h>

// KAN 3x3 convolution, uniform cubic B-spline closed form.
// x: (32, 256, 256) f32 in [0,1), base_weight: (3,3), spline_weight: (3,3,8)
// out: (32, 254, 254) f32

namespace {
constexpr int H  = 256, W  = 256;
constexpr int Ho = 254, Wo = 254;
constexpr int NB = 8;          // GRID_SIZE + SPLINE_ORDER
constexpr int TW = 4, TH = 4;  // per-thread output tile
constexpr int BTX = 32, BTY = 8;  // 256 threads; block covers 128x32 outputs
}

__global__ __launch_bounds__(BTX * BTY)
void kan_conv_kernel(const float* __restrict__ x,
                     const float* __restrict__ bw,
                     const float* __restrict__ sw,
                     float* __restrict__ out)
{
    // Shared table: swtab[o][p] = sw[p][2+o .. 5+o], o = knot-interval offset (0..2).
    __shared__ float4 swtab[3][9];
    const int tid = threadIdx.y * BTX + threadIdx.x;
    if (tid < 27) {
        const int o = tid / 9, p = tid % 9;
        swtab[o][p] = make_float4(sw[p * NB + 2 + o], sw[p * NB + 3 + o],
                                  sw[p * NB + 4 + o], sw[p * NB + 5 + o]);
    }
    float bwr[9];
#pragma unroll
    for (int p = 0; p < 9; ++p) bwr[p] = __ldg(&bw[p]);
    __syncthreads();

    const int batch = blockIdx.z;
    const int oc0 = (blockIdx.x * BTX + threadIdx.x) * TW;
    const int or0 = (blockIdx.y * BTY + threadIdx.y) * TH;
    const float* __restrict__ xb = x + batch * H * W;

    float acc[TH][TW];
#pragma unroll
    for (int i = 0; i < TH; ++i)
#pragma unroll
        for (int j = 0; j < TW; ++j) acc[i][j] = 0.0f;

#pragma unroll
    for (int r = 0; r < TH + 2; ++r) {
        const int ir = min(or0 + r, H - 1);
        const float* __restrict__ xrow = xb + ir * W;
#pragma unroll
        for (int cc = 0; cc < TW + 2; ++cc) {
            const int ic = min(oc0 + cc, W - 1);
            const float xv = __ldg(&xrow[ic]);

            // --- per-pixel transform ---
            // knot interval: grid[i] = (i-3)*0.4 - 1  =>  scaled = x*2.5 + 5.5
            float scaled = fmaf(xv, 2.5f, 5.5f);
            float fi = floorf(scaled);
            fi = fminf(fmaxf(fi, 5.0f), 7.0f);
            const float t  = scaled - fi;
            const int   o  = (int)fi - 5;         // 0..2
            const float t2 = t * t;
            const float u  = 1.0f - t;
            const float w0 = u * u * u * (1.0f / 6.0f);
            const float w3 = t2 * t * (1.0f / 6.0f);
            const float w1 = fmaf(t2, fmaf(0.5f, t, -1.0f), 2.0f / 3.0f);
            const float w2 = 1.0f - w0 - w1 - w3;     // partition of unity
            const float e  = __expf(-xv);
            const float s  = __fdividef(xv, 1.0f + e);  // silu(x)

            // --- accumulate into affected outputs ---
#pragma unroll
            for (int orr = 0; orr < TH; ++orr) {
                const int a = r - orr;
                if (a < 0 || a > 2) continue;
#pragma unroll
                for (int occ = 0; occ < TW; ++occ) {
                    const int b = cc - occ;
                    if (b < 0 || b > 2) continue;
                    const int p = a * 3 + b;
                    const float4 wv = swtab[o][p];
                    float v = fmaf(w0, wv.x,
                              fmaf(w1, wv.y,
                              fmaf(w2, wv.z,
                              fmaf(w3, wv.w, s * bwr[p]))));
                    acc[orr][occ] += v;
                }
            }
        }
    }

    float* __restrict__ ob = out + batch * Ho * Wo;
#pragma unroll
    for (int orr = 0; orr < TH; ++orr) {
        const int oh = or0 + orr;
        if (oh >= Ho) continue;
#pragma unroll
        for (int occ = 0; occ < TW; ++occ) {
            const int ow = oc0 + occ;
            if (ow < Wo) ob[oh * Wo + ow] = acc[orr][occ];
        }
    }
}

extern "C" void kernel_launch(void* const* d_in, const int* in_sizes, int n_in,
                              void* d_out, int out_size)
{
    const float* x  = (const float*)d_in[0];
    const float* bw = (const float*)d_in[1];
    const float* sw = (const float*)d_in[2];
    float* out = (float*)d_out;

    dim3 block(BTX, BTY);
    dim3 grid((Wo + BTX * TW - 1) / (BTX * TW),   // 2
              (Ho + BTY * TH - 1) / (BTY * TH),   // 8
              32);
    kan_conv_kernel<<<grid, block>>>(x, bw, sw, out);
}